// round 6
// baseline (speedup 1.0000x reference)
#include <cuda_runtime.h>
#include <math.h>

#define BB     2
#define NP     8192        // N*P
#define MM     16
#define BM     32          // BB*MM
#define CC     128
#define HH     256
#define NPAIR  (BB*NP*MM)  // 262144
#define TILE   32
#define TSTR   36          // padded row stride (floats) for sH [i][t]
#define NBLK   296         // 148 SMs * 2 resident blocks — ALL resident (deadlock-safe)

// ---------------- scratch (device globals; no allocation) ----------------
__device__ float  g_cond[BM*HH];    // conditioning rows  (B*M, H)
__device__ int    g_count;          // number of inside pairs   (reset by last block)
__device__ int    g_c1;             // phase-A barrier counter  (reset by last block)
__device__ int    g_c2;             // exit counter             (reset by last block)
__device__ int    g_idx[NPAIR];     // output index of each inside pair
__device__ float4 g_xt[NPAIR];      // Xt.xyz, w = bm as int bits

// ---------------- f32x2 packed helpers (sm_103a) ----------------
__device__ __forceinline__ void ffma2(unsigned long long& d,
                                      unsigned long long h, unsigned long long w) {
    asm("fma.rn.f32x2 %0, %1, %2, %0;" : "+l"(d) : "l"(h), "l"(w));
}
__device__ __forceinline__ unsigned long long splat2(float w) {
    unsigned long long r;
    asm("mov.b64 %0, {%1, %1};" : "=l"(r) : "r"(__float_as_uint(w)));
    return r;
}
__device__ __forceinline__ float2 unpack2(unsigned long long v) {
    unsigned lo, hi;
    asm("mov.b64 {%0, %1}, %2;" : "=r"(lo), "=r"(hi) : "l"(v));
    return make_float2(__uint_as_float(lo), __uint_as_float(hi));
}

// ---------------- layer inner loop: f32x2, pipelined weight loads ----------------
#define LAYER_LOOP(Wm)                                                            \
    {                                                                             \
        const float* wp_ = (Wm) + j;                                              \
        float wcur[8];                                                            \
        _Pragma("unroll")                                                         \
        for (int u = 0; u < 8; ++u) wcur[u] = wp_[u*HH];                          \
        for (int ib = 0; ib < HH; ib += 8) {                                      \
            float wnxt[8];                                                        \
            if (ib + 8 < HH) {                                                    \
                _Pragma("unroll")                                                 \
                for (int u = 0; u < 8; ++u) wnxt[u] = wp_[(ib+8+u)*HH];           \
            }                                                                     \
            _Pragma("unroll")                                                     \
            for (int u = 0; u < 8; ++u) {                                         \
                unsigned long long w2 = splat2(wcur[u]);                          \
                const ulonglong2* hp =                                            \
                    reinterpret_cast<const ulonglong2*>(&sH[(ib+u)*TSTR]);        \
                _Pragma("unroll")                                                 \
                for (int k = 0; k < 8; ++k) {                                     \
                    ulonglong2 q = hp[k];                                         \
                    ffma2(acc2[2*k],   q.x, w2);                                  \
                    ffma2(acc2[2*k+1], q.y, w2);                                  \
                }                                                                 \
            }                                                                     \
            _Pragma("unroll")                                                     \
            for (int u = 0; u < 8; ++u) wcur[u] = wnxt[u];                        \
        }                                                                         \
    }

__global__ void __launch_bounds__(256, 2) k_fused(
    const float* __restrict__ pts,  const float* __restrict__ trans,
    const float* __restrict__ rot,  const float* __restrict__ scale,
    const float* __restrict__ psf,  const float* __restrict__ Wc,
    const float* __restrict__ bc,
    const float* __restrict__ Wp,   const float* __restrict__ bp,
    const float* __restrict__ W1,   const float* __restrict__ b1,
    const float* __restrict__ W2,   const float* __restrict__ b2,
    const float* __restrict__ Wout, const float* __restrict__ bout,
    float* __restrict__ out)
{
    // phase-A smem
    __shared__ float sR[BM*9], sT[BM*3], sS[BM*3], sp[CC];
    __shared__ int   sWarp[8], sBase;
    // phase-B smem
    __shared__ __align__(16) float sH[HH*TSTR];   // 36.9 KB
    __shared__ float4 sXT[TILE];
    __shared__ int    sIdx[TILE];
    __shared__ float  sRed[8*TILE];

    int bid = blockIdx.x, tid = threadIdx.x;

    // ======================= PHASE A =======================
    // A0: zero-fill out (65536 float4 over 296*256 threads)
    {
        int gtid = bid*256 + tid;
        if (gtid < NPAIR/4)
            reinterpret_cast<float4*>(out)[gtid] = make_float4(0.f,0.f,0.f,0.f);
    }

    if (bid < BM) {
        // ---- conditioning row for bm = bid ----
        int bm = bid, jj = tid;
        if (tid < CC) sp[tid] = psf[bm*CC + tid];
        __syncthreads();
        float a0=0.f,a1=0.f,a2=0.f,a3=0.f,a4=0.f,a5=0.f,a6=0.f,a7=0.f;
        #pragma unroll 4
        for (int c = 0; c < CC; c += 8) {
            a0 = fmaf(sp[c+0], Wc[(c+0)*HH + jj], a0);
            a1 = fmaf(sp[c+1], Wc[(c+1)*HH + jj], a1);
            a2 = fmaf(sp[c+2], Wc[(c+2)*HH + jj], a2);
            a3 = fmaf(sp[c+3], Wc[(c+3)*HH + jj], a3);
            a4 = fmaf(sp[c+4], Wc[(c+4)*HH + jj], a4);
            a5 = fmaf(sp[c+5], Wc[(c+5)*HH + jj], a5);
            a6 = fmaf(sp[c+6], Wc[(c+6)*HH + jj], a6);
            a7 = fmaf(sp[c+7], Wc[(c+7)*HH + jj], a7);
        }
        g_cond[bm*HH + jj] = bc[jj] + ((a0+a1)+(a2+a3)) + ((a4+a5)+(a6+a7));
    }
    else if (bid < BM + 64) {
        // ---- mask + compaction: 64 blocks x 256 points ----
        if (tid < BM) {
            float w = rot[tid*4+0], x = rot[tid*4+1], y = rot[tid*4+2], z = rot[tid*4+3];
            float n = rsqrtf(w*w + x*x + y*y + z*z);
            w *= n; x *= n; y *= n; z *= n;
            float* R = &sR[tid*9];
            R[0] = 1.f - 2.f*(y*y + z*z); R[1] = 2.f*(x*y - w*z);       R[2] = 2.f*(x*z + w*y);
            R[3] = 2.f*(x*y + w*z);       R[4] = 1.f - 2.f*(x*x + z*z); R[5] = 2.f*(y*z - w*x);
            R[6] = 2.f*(x*z - w*y);       R[7] = 2.f*(y*z + w*x);       R[8] = 1.f - 2.f*(x*x + y*y);
        }
        if (tid < BM*3) { sT[tid] = trans[tid]; sS[tid] = scale[tid]; }
        __syncthreads();

        int idx = (bid - BM) * 256 + tid;      // 0..16383
        int b   = idx >> 13;
        float px = pts[idx*3+0], py = pts[idx*3+1], pz = pts[idx*3+2];

        unsigned maskbits = 0;
        #pragma unroll
        for (int m = 0; m < MM; ++m) {
            int bm = b*MM + m;
            float xc = px - sT[bm*3+0], yc = py - sT[bm*3+1], zc = pz - sT[bm*3+2];
            const float* R = &sR[bm*9];
            float xt = R[0]*xc + R[1]*yc + R[2]*zc;
            float yt = R[3]*xc + R[4]*yc + R[5]*zc;
            float zt = R[6]*xc + R[7]*yc + R[8]*zc;
            float fx = xt / sS[bm*3+0], fy = yt / sS[bm*3+1], fz = zt / sS[bm*3+2];
            if (fx*fx + fy*fy + fz*fz <= 1.0f) maskbits |= (1u << m);
        }

        int cnt  = __popc(maskbits);
        int lane = tid & 31, wid = tid >> 5;
        int incl = cnt;
        #pragma unroll
        for (int d = 1; d < 32; d <<= 1) {
            int v = __shfl_up_sync(0xffffffffu, incl, d);
            if (lane >= d) incl += v;
        }
        if (lane == 31) sWarp[wid] = incl;
        __syncthreads();
        if (tid == 0) {
            int s = 0;
            #pragma unroll
            for (int w = 0; w < 8; ++w) { int t = sWarp[w]; sWarp[w] = s; s += t; }
            sBase = s ? atomicAdd(&g_count, s) : 0;
        }
        __syncthreads();
        int off = sBase + sWarp[wid] + (incl - cnt);

        unsigned mb = maskbits;
        while (mb) {
            int m = __ffs(mb) - 1; mb &= mb - 1;
            int bm = b*MM + m;
            float xc = px - sT[bm*3+0], yc = py - sT[bm*3+1], zc = pz - sT[bm*3+2];
            const float* R = &sR[bm*9];
            float xt = R[0]*xc + R[1]*yc + R[2]*zc;
            float yt = R[3]*xc + R[4]*yc + R[5]*zc;
            float zt = R[6]*xc + R[7]*yc + R[8]*zc;
            g_idx[off] = idx*MM + m;
            g_xt[off]  = make_float4(xt, yt, zt, __int_as_float(bm));
            ++off;
        }
    }

    // ======================= device-wide barrier =======================
    __syncthreads();
    if (tid == 0) {
        __threadfence();
        atomicAdd(&g_c1, 1);
        while (*(volatile int*)&g_c1 < NBLK) { }
        __threadfence();
    }
    __syncthreads();

    int total = g_count;

    // ======================= PHASE B: fused MLP =======================
    int j    = tid;           // hidden column
    int lane = j & 31, wid = j >> 5;

    float wp0 = Wp[0*HH + j], wp1 = Wp[1*HH + j], wp2 = Wp[2*HH + j];
    float bpj = bp[j], b1j = b1[j], b2j = b2[j], wOj = Wout[j];
    float bo  = bout[0];

    for (int base = bid * TILE; base < total; base += NBLK * TILE) {
        int nt = min(TILE, total - base);
        __syncthreads();
        if (j < TILE) {
            if (j < nt) { sXT[j] = g_xt[base + j]; sIdx[j] = g_idx[base + j]; }
            else        { sXT[j] = make_float4(0.f,0.f,0.f,__int_as_float(0)); sIdx[j] = -1; }
        }
        __syncthreads();

        unsigned long long acc2[TILE/2];

        // ---- phase 1: relu(net0) -> sH ----
        {
            float v[TILE];
            #pragma unroll
            for (int t = 0; t < TILE; ++t) {
                float4 xt = sXT[t];
                int bm = __float_as_int(xt.w);
                float n0 = fmaf(wp0, xt.x, fmaf(wp1, xt.y, fmaf(wp2, xt.z,
                           bpj + __ldg(&g_cond[bm*HH + j]))));
                v[t] = fmaxf(n0, 0.f);
            }
            #pragma unroll
            for (int t = 0; t < TILE; t += 4)
                *reinterpret_cast<float4*>(&sH[j*TSTR + t]) =
                    make_float4(v[t], v[t+1], v[t+2], v[t+3]);
        }
        __syncthreads();

        // ---- layer 1 ----
        {
            unsigned long long binit = splat2(b1j);
            #pragma unroll
            for (int k = 0; k < TILE/2; ++k) acc2[k] = binit;
            LAYER_LOOP(W1);
        }
        __syncthreads();
        {
            float v[TILE];
            #pragma unroll
            for (int k = 0; k < TILE/2; ++k) {
                float2 p = unpack2(acc2[k]);
                v[2*k]   = fmaxf(p.x, 0.f);
                v[2*k+1] = fmaxf(p.y, 0.f);
            }
            #pragma unroll
            for (int t = 0; t < TILE; t += 4)
                *reinterpret_cast<float4*>(&sH[j*TSTR + t]) =
                    make_float4(v[t], v[t+1], v[t+2], v[t+3]);
        }
        __syncthreads();

        // ---- layer 2 ----
        {
            unsigned long long binit = splat2(b2j);
            #pragma unroll
            for (int k = 0; k < TILE/2; ++k) acc2[k] = binit;
            LAYER_LOOP(W2);
        }

        // ---- occ partials: relu(net0(recomputed) + t2) * Wout[j] ----
        float a[TILE];
        #pragma unroll
        for (int t = 0; t < TILE; ++t) {
            float4 xt = sXT[t];
            int bm = __float_as_int(xt.w);
            float n0 = fmaf(wp0, xt.x, fmaf(wp1, xt.y, fmaf(wp2, xt.z,
                       bpj + __ldg(&g_cond[bm*HH + j]))));
            float2 p = unpack2(acc2[t>>1]);
            float dx = (t & 1) ? p.y : p.x;
            a[t] = fmaxf(n0 + dx, 0.f) * wOj;
        }
        #pragma unroll
        for (int t = 0; t < TILE; ++t) {
            float s = a[t];
            s += __shfl_xor_sync(0xffffffffu, s, 16);
            s += __shfl_xor_sync(0xffffffffu, s, 8);
            s += __shfl_xor_sync(0xffffffffu, s, 4);
            s += __shfl_xor_sync(0xffffffffu, s, 2);
            s += __shfl_xor_sync(0xffffffffu, s, 1);
            if (lane == 0) sRed[wid*TILE + t] = s;
        }
        __syncthreads();
        if (j < TILE) {
            float s = 0.f;
            #pragma unroll
            for (int w = 0; w < 8; ++w) s += sRed[w*TILE + j];
            int oidx = sIdx[j];
            if (oidx >= 0) {
                float occ = s + bo;
                out[oidx] = 1.0f / (1.0f + expf(-10.0f * occ));
            }
        }
    }

    // ======================= exit: last block resets state =======================
    __syncthreads();
    if (tid == 0) {
        __threadfence();
        int old = atomicAdd(&g_c2, 1);
        if (old == NBLK - 1) {      // last block out resets for next graph replay
            g_count = 0;
            g_c1 = 0;
            g_c2 = 0;
        }
    }
}

// ---------------- launcher ----------------
extern "C" void kernel_launch(void* const* d_in, const int* in_sizes, int n_in,
                              void* d_out, int out_size)
{
    const float* ray   = (const float*)d_in[0];
    const float* trans = (const float*)d_in[1];
    const float* rot   = (const float*)d_in[2];
    const float* scl   = (const float*)d_in[3];
    const float* psf   = (const float*)d_in[4];
    const float* Wp    = (const float*)d_in[5];
    const float* bp    = (const float*)d_in[6];
    const float* Wc    = (const float*)d_in[7];
    const float* bc    = (const float*)d_in[8];
    const float* W1    = (const float*)d_in[9];
    const float* b1    = (const float*)d_in[10];
    const float* W2    = (const float*)d_in[11];
    const float* b2    = (const float*)d_in[12];
    const float* Wout  = (const float*)d_in[13];
    const float* bout  = (const float*)d_in[14];
    float* out = (float*)d_out;

    k_fused<<<NBLK, 256>>>(ray, trans, rot, scl, psf, Wc, bc,
                           Wp, bp, W1, b1, W2, b2, Wout, bout, out);
}